// round 5
// baseline (speedup 1.0000x reference)
#include <cuda_runtime.h>

// OU Euler-Maruyama: x_{t+1} = a*x_t + b_t,  a = 1 - gamma*dt (const per chain).
// One warp per (chain, time-segment): 2 segments per chain -> 4096 warps.
// Segment 1 starts 24 tiles (3072 steps) early with x=0: since a <= 0.995,
// a^3072 <= e^-15.4, the true-state influence is < 2e-7 by its first stored
// tile -> deterministic error ~1e-6, far under the 1e-3 threshold.
// Tile = 128 steps: lane L holds float4 (coalesced LDG.128/STG.128);
// constant-coefficient affine warp scan (5 SHFL+FMA steps).
// PF=8 register prefetch ring: 4KB/warp in flight, ~112KB/SM at 28 warps/SM.

#define T_STEPS 20000
#define NV4     5000            // T_STEPS/4 float4s per chain
#define N_CHAIN 2048            // 32 * 64
#define PF      8               // prefetch depth (tiles)
#define SPLIT   88              // seg0 stores tiles [0,88), seg1 [88,157)
#define WSTART  64              // seg1 warmup begins at tile 64 (24-tile warmup)
#define MACRO0  11              // 88 tiles  = 11*PF
#define MACRO1  12              // 96 tiles  = 12*PF (64..160, tail guarded)

__device__ __forceinline__ float4 load_tile(const float4* __restrict__ np,
                                            int tile, int lane) {
    int idx = tile * 32 + lane;
    if (idx < NV4) return np[idx];
    return make_float4(0.f, 0.f, 0.f, 0.f);
}

__global__ __launch_bounds__(128)
void oup_kernel(const float* __restrict__ theta,
                const float* __restrict__ noise,
                float*       __restrict__ out)
{
    const int warp = (blockIdx.x * blockDim.x + threadIdx.x) >> 5;
    const int lane = threadIdx.x & 31;

    const int chain = warp >> 1;             // (n,m) chain id
    const int half  = warp & 1;              // 0: front segment, 1: back segment
    const int n     = chain >> 6;            // chain-param row

    const float gamma = theta[n * 4 + 0];
    const float mu    = theta[n * 4 + 1];
    const float sigma = theta[n * 4 + 2];
    // seg1 starts from 0; contribution of the true state has decayed to <2e-7
    // by its first stored tile.
    float x = half ? 0.0f : theta[n * 4 + 3];

    const float a   = 1.0f - gamma * 0.01f;  // dt = 0.01
    const float c0  = gamma * mu * 0.01f;
    const float ssd = sigma * 0.1f;          // sqrt(dt) = 0.1

    const float a2   = a * a;
    const float a4   = a2 * a2;
    const float a8   = a4 * a4;
    const float a16  = a8 * a8;
    const float a32  = a16 * a16;
    const float a64  = a32 * a32;
    const float a128 = a64 * a64;

    // a^(4*lane): exclusive-prefix coefficient for this lane's starting state
    float alane = 1.0f;
    if (lane & 1)  alane *= a4;
    if (lane & 2)  alane *= a8;
    if (lane & 4)  alane *= a16;
    if (lane & 8)  alane *= a32;
    if (lane & 16) alane *= a64;

    const float4* __restrict__ np = (const float4*)(noise + (size_t)chain * T_STEPS);
    float4*       __restrict__ op = (float4*)(out + (size_t)chain * T_STEPS);

    const int start      = half ? WSTART : 0;
    const int store_from = half ? SPLIT  : 0;
    const int n_macro    = half ? MACRO1 : MACRO0;

    // Prefetch ring
    float4 buf[PF];
#pragma unroll
    for (int k = 0; k < PF; ++k) buf[k] = load_tile(np, start + k, lane);

    auto process = [&](float4 v, int tile) {
        const float b0 = fmaf(ssd, v.x, c0);
        const float b1 = fmaf(ssd, v.y, c0);
        const float b2 = fmaf(ssd, v.z, c0);
        const float b3 = fmaf(ssd, v.w, c0);

        // Thread-local aggregate offset over 4 steps (coefficient a^4)
        float B = b0;
        B = fmaf(a, B, b1);
        B = fmaf(a, B, b2);
        B = fmaf(a, B, b3);

        // Warp inclusive affine scan (Hillis-Steele, weights a^(4*2^s))
        float t;
        t = __shfl_up_sync(0xFFFFFFFFu, B, 1);  if (lane >= 1)  B = fmaf(a4,  t, B);
        t = __shfl_up_sync(0xFFFFFFFFu, B, 2);  if (lane >= 2)  B = fmaf(a8,  t, B);
        t = __shfl_up_sync(0xFFFFFFFFu, B, 4);  if (lane >= 4)  B = fmaf(a16, t, B);
        t = __shfl_up_sync(0xFFFFFFFFu, B, 8);  if (lane >= 8)  B = fmaf(a32, t, B);
        t = __shfl_up_sync(0xFFFFFFFFu, B, 16); if (lane >= 16) B = fmaf(a64, t, B);

        float Bexcl = __shfl_up_sync(0xFFFFFFFFu, B, 1);
        if (lane == 0) Bexcl = 0.0f;
        const float Btop = __shfl_sync(0xFFFFFFFFu, B, 31);

        // State entering this lane's 4 steps
        const float xs = fmaf(alane, x, Bexcl);
        const float y0 = fmaf(a, xs, b0);
        const float y1 = fmaf(a, y0, b1);
        const float y2 = fmaf(a, y1, b2);
        const float y3 = fmaf(a, y2, b3);

        const int idx = tile * 32 + lane;
        if (tile >= store_from && idx < NV4)
            op[idx] = make_float4(y0, y1, y2, y3);

        // Advance carry 128 steps (uniform across warp)
        x = fmaf(a128, x, Btop);
    };

    for (int mi = 0; mi < n_macro; ++mi) {
#pragma unroll
        for (int k = 0; k < PF; ++k) {
            const int i = start + mi * PF + k;
            float4 v = buf[k];
            buf[k] = load_tile(np, i + PF, lane);   // guarded refill (OOB -> 0)
            process(v, i);
        }
    }
}

extern "C" void kernel_launch(void* const* d_in, const int* in_sizes, int n_in,
                              void* d_out, int out_size)
{
    const float* theta = (const float*)d_in[0];   // [32,4]
    const float* noise = (const float*)d_in[1];   // [32,64,20000]
    float* out = (float*)d_out;                   // [32,64,20000]
    (void)in_sizes; (void)n_in; (void)out_size;
    // 4096 warps = 2 segments x 2048 chains; 128 threads/block -> 1024 blocks
    oup_kernel<<<N_CHAIN * 2 / 4, 128>>>(theta, noise, out);
}

// round 7
// speedup vs baseline: 1.0708x; 1.0708x over previous
#include <cuda_runtime.h>

// OU Euler-Maruyama: x_{t+1} = a*x_t + b_t,  a = 1 - gamma*dt (const per chain).
// One warp per (n,m) chain (2048 warps) — R4 showed splitting chains across
// more warps REDUCES achieved HBM (queue contention); reverted.
// Tile = 128 steps: lane L holds float4 (coalesced LDG.128/STG.128);
// constant-coefficient affine warp scan (5 SHFL+FMA steps).
// PF=12 register prefetch ring: 6KB/warp in flight (~84KB/SM @13.8 warps/SM),
// 3x the ~27KB needed to cover loaded DRAM latency; per-lane MLP=12 << 55 cap.
// Tiles 0..155 are unguarded (156*32=4992 <= 5000); only tile 156 is guarded.

#define T_STEPS 20000
#define NV4     5000            // T_STEPS/4 float4s per chain
#define N_CHAIN 2048            // 32 * 64
#define PF      12              // prefetch depth (tiles)
#define MACRO   13              // 13*12 = 156 unguarded tiles, then tail tile 156

__device__ __forceinline__ float4 load_tile(const float4* __restrict__ np,
                                            int tile, int lane) {
    int idx = tile * 32 + lane;
    if (idx < NV4) return np[idx];
    return make_float4(0.f, 0.f, 0.f, 0.f);
}

__global__ __launch_bounds__(128)
void oup_kernel(const float* __restrict__ theta,
                const float* __restrict__ noise,
                float*       __restrict__ out)
{
    const int warp = (blockIdx.x * blockDim.x + threadIdx.x) >> 5;
    const int lane = threadIdx.x & 31;
    if (warp >= N_CHAIN) return;

    const int n = warp >> 6;                 // chain-param row
    const float gamma = theta[n * 4 + 0];
    const float mu    = theta[n * 4 + 1];
    const float sigma = theta[n * 4 + 2];
    float x           = theta[n * 4 + 3];    // running state (carry)

    const float a   = 1.0f - gamma * 0.01f;  // dt = 0.01
    const float c0  = gamma * mu * 0.01f;
    const float ssd = sigma * 0.1f;          // sqrt(dt) = 0.1

    const float a2   = a * a;
    const float a4   = a2 * a2;
    const float a8   = a4 * a4;
    const float a16  = a8 * a8;
    const float a32  = a16 * a16;
    const float a64  = a32 * a32;
    const float a128 = a64 * a64;

    // a^(4*lane): exclusive-prefix coefficient for this lane's starting state
    float alane = 1.0f;
    if (lane & 1)  alane *= a4;
    if (lane & 2)  alane *= a8;
    if (lane & 4)  alane *= a16;
    if (lane & 8)  alane *= a32;
    if (lane & 16) alane *= a64;

    const float4* __restrict__ np = (const float4*)(noise + (size_t)warp * T_STEPS);
    float4*       __restrict__ op = (float4*)(out + (size_t)warp * T_STEPS);

    // Prefetch ring (tiles 0..PF-1 all in-bounds: PF*32 <= 5000)
    float4 buf[PF];
#pragma unroll
    for (int k = 0; k < PF; ++k) buf[k] = np[k * 32 + lane];

    // Process one 128-step tile held in v. guarded=true only for tile 156.
    auto process = [&](float4 v, int tile, bool guarded) {
        const float b0 = fmaf(ssd, v.x, c0);
        const float b1 = fmaf(ssd, v.y, c0);
        const float b2 = fmaf(ssd, v.z, c0);
        const float b3 = fmaf(ssd, v.w, c0);

        // Thread-local aggregate offset over 4 steps (coefficient a^4)
        float B = b0;
        B = fmaf(a, B, b1);
        B = fmaf(a, B, b2);
        B = fmaf(a, B, b3);

        // Warp inclusive affine scan (Hillis-Steele, weights a^(4*2^s))
        float t;
        t = __shfl_up_sync(0xFFFFFFFFu, B, 1);  if (lane >= 1)  B = fmaf(a4,  t, B);
        t = __shfl_up_sync(0xFFFFFFFFu, B, 2);  if (lane >= 2)  B = fmaf(a8,  t, B);
        t = __shfl_up_sync(0xFFFFFFFFu, B, 4);  if (lane >= 4)  B = fmaf(a16, t, B);
        t = __shfl_up_sync(0xFFFFFFFFu, B, 8);  if (lane >= 8)  B = fmaf(a32, t, B);
        t = __shfl_up_sync(0xFFFFFFFFu, B, 16); if (lane >= 16) B = fmaf(a64, t, B);

        float Bexcl = __shfl_up_sync(0xFFFFFFFFu, B, 1);
        if (lane == 0) Bexcl = 0.0f;
        const float Btop = __shfl_sync(0xFFFFFFFFu, B, 31);

        // State entering this lane's 4 steps
        const float xs = fmaf(alane, x, Bexcl);
        const float y0 = fmaf(a, xs, b0);
        const float y1 = fmaf(a, y0, b1);
        const float y2 = fmaf(a, y1, b2);
        const float y3 = fmaf(a, y2, b3);

        const int idx = tile * 32 + lane;
        if (!guarded || idx < NV4)
            op[idx] = make_float4(y0, y1, y2, y3);

        // Advance carry 128 steps (uniform across warp)
        x = fmaf(a128, x, Btop);
    };

    for (int mi = 0; mi < MACRO; ++mi) {
#pragma unroll
        for (int k = 0; k < PF; ++k) {
            const int i = mi * PF + k;
            float4 v = buf[k];
            buf[k] = load_tile(np, i + PF, lane);   // guarded refill (OOB -> 0)
            process(v, i, false);
        }
    }
    process(buf[0], MACRO * PF, true);   // tail tile 156 (partial, guarded)
}

extern "C" void kernel_launch(void* const* d_in, const int* in_sizes, int n_in,
                              void* d_out, int out_size)
{
    const float* theta = (const float*)d_in[0];   // [32,4]
    const float* noise = (const float*)d_in[1];   // [32,64,20000]
    float* out = (float*)d_out;                   // [32,64,20000]
    (void)in_sizes; (void)n_in; (void)out_size;
    oup_kernel<<<N_CHAIN / 4, 128>>>(theta, noise, out);
}

// round 8
// speedup vs baseline: 1.1140x; 1.0403x over previous
#include <cuda_runtime.h>

// OU Euler-Maruyama: x_{t+1} = a*x_t + b_t,  a = 1 - gamma*dt (const per chain).
// One warp per (n,m) chain (2048 warps). Tile = 128 steps (lane L: float4,
// coalesced LDG.128/STG.128). Constant-coefficient affine warp scan.
// R7: 4-tile interleaved scan — the per-tile B-scan is carry-independent, so
// 4 tiles' shuffle rounds run with 4-way ILP (amortizes 26cyc SHFL latency);
// only a 1-FMA/tile carry chain is serial. Streaming hints (__ldcs/__stcs)
// keep the zero-reuse 328MB stream from thrashing L2.
// PF=8 register prefetch ring (4KB/warp in flight, saturated per R6).

#define T_STEPS 20000
#define NV4     5000            // T_STEPS/4 float4s per chain
#define N_CHAIN 2048            // 32 * 64
#define PF      8               // prefetch depth (tiles)
#define NMAIN   19              // 19*8 = 152 tiles in main loop

__device__ __forceinline__ float4 load_tile(const float4* __restrict__ np,
                                            int tile, int lane) {
    int idx = tile * 32 + lane;
    if (idx < NV4) return __ldcs(np + idx);
    return make_float4(0.f, 0.f, 0.f, 0.f);
}

__global__ __launch_bounds__(128)
void oup_kernel(const float* __restrict__ theta,
                const float* __restrict__ noise,
                float*       __restrict__ out)
{
    const int warp = (blockIdx.x * blockDim.x + threadIdx.x) >> 5;
    const int lane = threadIdx.x & 31;
    if (warp >= N_CHAIN) return;

    const int n = warp >> 6;                 // chain-param row
    const float gamma = theta[n * 4 + 0];
    const float mu    = theta[n * 4 + 1];
    const float sigma = theta[n * 4 + 2];
    float x           = theta[n * 4 + 3];    // running state (carry)

    const float a   = 1.0f - gamma * 0.01f;  // dt = 0.01
    const float c0  = gamma * mu * 0.01f;
    const float ssd = sigma * 0.1f;          // sqrt(dt) = 0.1

    const float a2   = a * a;
    const float a4   = a2 * a2;
    const float a8   = a4 * a4;
    const float a16  = a8 * a8;
    const float a32  = a16 * a16;
    const float a64  = a32 * a32;
    const float a128 = a64 * a64;

    // a^(4*lane): exclusive-prefix coefficient for this lane's start state
    float alane = 1.0f;
    if (lane & 1)  alane *= a4;
    if (lane & 2)  alane *= a8;
    if (lane & 4)  alane *= a16;
    if (lane & 8)  alane *= a32;
    if (lane & 16) alane *= a64;

    const float4* __restrict__ np = (const float4*)(noise + (size_t)warp * T_STEPS);
    float4*       __restrict__ op = (float4*)(out + (size_t)warp * T_STEPS);

    // Prefetch ring (tiles 0..7 in-bounds)
    float4 buf[PF];
#pragma unroll
    for (int k = 0; k < PF; ++k) buf[k] = __ldcs(np + k * 32 + lane);

    // ---- 4-tile group: interleaved B-scans (ILP=4), serial carry apply ----
    auto group4 = [&](const float4* v, int tile0) {
        float b[4][4], B[4];
#pragma unroll
        for (int j = 0; j < 4; ++j) {
            b[j][0] = fmaf(ssd, v[j].x, c0);
            b[j][1] = fmaf(ssd, v[j].y, c0);
            b[j][2] = fmaf(ssd, v[j].z, c0);
            b[j][3] = fmaf(ssd, v[j].w, c0);
            float t = b[j][0];
            t = fmaf(a, t, b[j][1]);
            t = fmaf(a, t, b[j][2]);
            B[j] = fmaf(a, t, b[j][3]);
        }
        // 5 scan rounds, 4 independent SHFL+FMA per round
#pragma unroll
        for (int s = 0; s < 5; ++s) {
            const int   d = 1 << s;
            const float w = (s == 0) ? a4 : (s == 1) ? a8 : (s == 2) ? a16
                          : (s == 3) ? a32 : a64;
            float t0 = __shfl_up_sync(0xFFFFFFFFu, B[0], d);
            float t1 = __shfl_up_sync(0xFFFFFFFFu, B[1], d);
            float t2 = __shfl_up_sync(0xFFFFFFFFu, B[2], d);
            float t3 = __shfl_up_sync(0xFFFFFFFFu, B[3], d);
            if (lane >= d) {
                B[0] = fmaf(w, t0, B[0]);
                B[1] = fmaf(w, t1, B[1]);
                B[2] = fmaf(w, t2, B[2]);
                B[3] = fmaf(w, t3, B[3]);
            }
        }
        float Bexcl[4], Btop[4];
#pragma unroll
        for (int j = 0; j < 4; ++j) {
            Bexcl[j] = __shfl_up_sync(0xFFFFFFFFu, B[j], 1);
            if (lane == 0) Bexcl[j] = 0.0f;
            Btop[j] = __shfl_sync(0xFFFFFFFFu, B[j], 31);
        }
        // Serial carry across the 4 tiles (1 FMA deep per tile); outputs ILP
#pragma unroll
        for (int j = 0; j < 4; ++j) {
            const float xs = fmaf(alane, x, Bexcl[j]);
            const float y0 = fmaf(a, xs, b[j][0]);
            const float y1 = fmaf(a, y0, b[j][1]);
            const float y2 = fmaf(a, y1, b[j][2]);
            const float y3 = fmaf(a, y2, b[j][3]);
            __stcs(op + (tile0 + j) * 32 + lane, make_float4(y0, y1, y2, y3));
            x = fmaf(a128, x, Btop[j]);
        }
    };

    // Main: 19 macro-iters x 2 groups of 4 = tiles 0..151 (all unguarded)
    for (int mi = 0; mi < NMAIN; ++mi) {
#pragma unroll
        for (int h = 0; h < 2; ++h) {
            const int i0 = mi * PF + h * 4;
            float4 v[4];
#pragma unroll
            for (int j = 0; j < 4; ++j) v[j] = buf[h * 4 + j];
#pragma unroll
            for (int j = 0; j < 4; ++j)
                buf[h * 4 + j] = load_tile(np, i0 + PF + j, lane);  // batched refill
            group4(v, i0);
        }
    }
    // Tiles 152..155 (in-bounds: 156*32 = 4992 <= 5000), from ring, no refill
    {
        float4 v[4];
#pragma unroll
        for (int j = 0; j < 4; ++j) v[j] = buf[j];
        group4(v, NMAIN * PF);
    }
    // Tail tile 156 (partial: lanes with idx < 5000)
    {
        const float4 v = buf[4];
        const float b0 = fmaf(ssd, v.x, c0);
        const float b1 = fmaf(ssd, v.y, c0);
        const float b2 = fmaf(ssd, v.z, c0);
        const float b3 = fmaf(ssd, v.w, c0);
        float B = b0;
        B = fmaf(a, B, b1);
        B = fmaf(a, B, b2);
        B = fmaf(a, B, b3);
        float t;
        t = __shfl_up_sync(0xFFFFFFFFu, B, 1);  if (lane >= 1)  B = fmaf(a4,  t, B);
        t = __shfl_up_sync(0xFFFFFFFFu, B, 2);  if (lane >= 2)  B = fmaf(a8,  t, B);
        t = __shfl_up_sync(0xFFFFFFFFu, B, 4);  if (lane >= 4)  B = fmaf(a16, t, B);
        t = __shfl_up_sync(0xFFFFFFFFu, B, 8);  if (lane >= 8)  B = fmaf(a32, t, B);
        t = __shfl_up_sync(0xFFFFFFFFu, B, 16); if (lane >= 16) B = fmaf(a64, t, B);
        float Bexcl = __shfl_up_sync(0xFFFFFFFFu, B, 1);
        if (lane == 0) Bexcl = 0.0f;
        const float xs = fmaf(alane, x, Bexcl);
        const float y0 = fmaf(a, xs, b0);
        const float y1 = fmaf(a, y0, b1);
        const float y2 = fmaf(a, y1, b2);
        const float y3 = fmaf(a, y2, b3);
        const int idx = (NMAIN * PF + 4) * 32 + lane;
        if (idx < NV4) __stcs(op + idx, make_float4(y0, y1, y2, y3));
    }
}

extern "C" void kernel_launch(void* const* d_in, const int* in_sizes, int n_in,
                              void* d_out, int out_size)
{
    const float* theta = (const float*)d_in[0];   // [32,4]
    const float* noise = (const float*)d_in[1];   // [32,64,20000]
    float* out = (float*)d_out;                   // [32,64,20000]
    (void)in_sizes; (void)n_in; (void)out_size;
    oup_kernel<<<N_CHAIN / 4, 128>>>(theta, noise, out);
}

// round 9
// speedup vs baseline: 1.1298x; 1.0142x over previous
#include <cuda_runtime.h>

// OU Euler-Maruyama: x_{t+1} = a*x_t + b_t,  a = 1 - gamma*dt (const per chain).
// One warp per (n,m) chain (2048 warps). Tile = 128 steps (lane L: float4,
// coalesced LDG.128/STG.128). Constant-coefficient affine warp scan with
// 4-tile interleaving (scan rounds have ILP=4; only 1-FMA/tile carry chain
// is serial). Streaming hints (__ldcs/__stcs) for the zero-reuse 328MB.
// R8: 64-thread CTAs. 512x128t gave 512/148 = 3.46 CTAs/SM -> 68 SMs ran 4
// CTAs vs 80 running 3 (13.5% tail imbalance). 1024x64t -> 6.92/SM, 1.2%.

#define T_STEPS 20000
#define NV4     5000            // T_STEPS/4 float4s per chain
#define N_CHAIN 2048            // 32 * 64
#define PF      8               // prefetch depth (tiles)
#define NMAIN   19              // 19*8 = 152 tiles in main loop

__device__ __forceinline__ float4 load_tile(const float4* __restrict__ np,
                                            int tile, int lane) {
    int idx = tile * 32 + lane;
    if (idx < NV4) return __ldcs(np + idx);
    return make_float4(0.f, 0.f, 0.f, 0.f);
}

__global__ __launch_bounds__(64)
void oup_kernel(const float* __restrict__ theta,
                const float* __restrict__ noise,
                float*       __restrict__ out)
{
    const int warp = (blockIdx.x * blockDim.x + threadIdx.x) >> 5;
    const int lane = threadIdx.x & 31;
    if (warp >= N_CHAIN) return;

    const int n = warp >> 6;                 // chain-param row
    const float gamma = theta[n * 4 + 0];
    const float mu    = theta[n * 4 + 1];
    const float sigma = theta[n * 4 + 2];
    float x           = theta[n * 4 + 3];    // running state (carry)

    const float a   = 1.0f - gamma * 0.01f;  // dt = 0.01
    const float c0  = gamma * mu * 0.01f;
    const float ssd = sigma * 0.1f;          // sqrt(dt) = 0.1

    const float a2   = a * a;
    const float a4   = a2 * a2;
    const float a8   = a4 * a4;
    const float a16  = a8 * a8;
    const float a32  = a16 * a16;
    const float a64  = a32 * a32;
    const float a128 = a64 * a64;

    // a^(4*lane): exclusive-prefix coefficient for this lane's start state
    float alane = 1.0f;
    if (lane & 1)  alane *= a4;
    if (lane & 2)  alane *= a8;
    if (lane & 4)  alane *= a16;
    if (lane & 8)  alane *= a32;
    if (lane & 16) alane *= a64;

    const float4* __restrict__ np = (const float4*)(noise + (size_t)warp * T_STEPS);
    float4*       __restrict__ op = (float4*)(out + (size_t)warp * T_STEPS);

    // Prefetch ring (tiles 0..7 in-bounds)
    float4 buf[PF];
#pragma unroll
    for (int k = 0; k < PF; ++k) buf[k] = __ldcs(np + k * 32 + lane);

    // ---- 4-tile group: interleaved B-scans (ILP=4), serial carry apply ----
    auto group4 = [&](const float4* v, int tile0) {
        float b[4][4], B[4];
#pragma unroll
        for (int j = 0; j < 4; ++j) {
            b[j][0] = fmaf(ssd, v[j].x, c0);
            b[j][1] = fmaf(ssd, v[j].y, c0);
            b[j][2] = fmaf(ssd, v[j].z, c0);
            b[j][3] = fmaf(ssd, v[j].w, c0);
            float t = b[j][0];
            t = fmaf(a, t, b[j][1]);
            t = fmaf(a, t, b[j][2]);
            B[j] = fmaf(a, t, b[j][3]);
        }
        // 5 scan rounds, 4 independent SHFL+FMA per round
#pragma unroll
        for (int s = 0; s < 5; ++s) {
            const int   d = 1 << s;
            const float w = (s == 0) ? a4 : (s == 1) ? a8 : (s == 2) ? a16
                          : (s == 3) ? a32 : a64;
            float t0 = __shfl_up_sync(0xFFFFFFFFu, B[0], d);
            float t1 = __shfl_up_sync(0xFFFFFFFFu, B[1], d);
            float t2 = __shfl_up_sync(0xFFFFFFFFu, B[2], d);
            float t3 = __shfl_up_sync(0xFFFFFFFFu, B[3], d);
            if (lane >= d) {
                B[0] = fmaf(w, t0, B[0]);
                B[1] = fmaf(w, t1, B[1]);
                B[2] = fmaf(w, t2, B[2]);
                B[3] = fmaf(w, t3, B[3]);
            }
        }
        float Bexcl[4], Btop[4];
#pragma unroll
        for (int j = 0; j < 4; ++j) {
            Bexcl[j] = __shfl_up_sync(0xFFFFFFFFu, B[j], 1);
            if (lane == 0) Bexcl[j] = 0.0f;
            Btop[j] = __shfl_sync(0xFFFFFFFFu, B[j], 31);
        }
        // Serial carry across the 4 tiles (1 FMA deep per tile); outputs ILP
#pragma unroll
        for (int j = 0; j < 4; ++j) {
            const float xs = fmaf(alane, x, Bexcl[j]);
            const float y0 = fmaf(a, xs, b[j][0]);
            const float y1 = fmaf(a, y0, b[j][1]);
            const float y2 = fmaf(a, y1, b[j][2]);
            const float y3 = fmaf(a, y2, b[j][3]);
            __stcs(op + (tile0 + j) * 32 + lane, make_float4(y0, y1, y2, y3));
            x = fmaf(a128, x, Btop[j]);
        }
    };

    // Main: 19 macro-iters x 2 groups of 4 = tiles 0..151 (all unguarded)
    for (int mi = 0; mi < NMAIN; ++mi) {
#pragma unroll
        for (int h = 0; h < 2; ++h) {
            const int i0 = mi * PF + h * 4;
            float4 v[4];
#pragma unroll
            for (int j = 0; j < 4; ++j) v[j] = buf[h * 4 + j];
#pragma unroll
            for (int j = 0; j < 4; ++j)
                buf[h * 4 + j] = load_tile(np, i0 + PF + j, lane);  // batched refill
            group4(v, i0);
        }
    }
    // Tiles 152..155 (in-bounds: 156*32 = 4992 <= 5000), from ring, no refill
    {
        float4 v[4];
#pragma unroll
        for (int j = 0; j < 4; ++j) v[j] = buf[j];
        group4(v, NMAIN * PF);
    }
    // Tail tile 156 (partial: lanes with idx < 5000)
    {
        const float4 v = buf[4];
        const float b0 = fmaf(ssd, v.x, c0);
        const float b1 = fmaf(ssd, v.y, c0);
        const float b2 = fmaf(ssd, v.z, c0);
        const float b3 = fmaf(ssd, v.w, c0);
        float B = b0;
        B = fmaf(a, B, b1);
        B = fmaf(a, B, b2);
        B = fmaf(a, B, b3);
        float t;
        t = __shfl_up_sync(0xFFFFFFFFu, B, 1);  if (lane >= 1)  B = fmaf(a4,  t, B);
        t = __shfl_up_sync(0xFFFFFFFFu, B, 2);  if (lane >= 2)  B = fmaf(a8,  t, B);
        t = __shfl_up_sync(0xFFFFFFFFu, B, 4);  if (lane >= 4)  B = fmaf(a16, t, B);
        t = __shfl_up_sync(0xFFFFFFFFu, B, 8);  if (lane >= 8)  B = fmaf(a32, t, B);
        t = __shfl_up_sync(0xFFFFFFFFu, B, 16); if (lane >= 16) B = fmaf(a64, t, B);
        float Bexcl = __shfl_up_sync(0xFFFFFFFFu, B, 1);
        if (lane == 0) Bexcl = 0.0f;
        const float xs = fmaf(alane, x, Bexcl);
        const float y0 = fmaf(a, xs, b0);
        const float y1 = fmaf(a, y0, b1);
        const float y2 = fmaf(a, y1, b2);
        const float y3 = fmaf(a, y2, b3);
        const int idx = (NMAIN * PF + 4) * 32 + lane;
        if (idx < NV4) __stcs(op + idx, make_float4(y0, y1, y2, y3));
    }
}

extern "C" void kernel_launch(void* const* d_in, const int* in_sizes, int n_in,
                              void* d_out, int out_size)
{
    const float* theta = (const float*)d_in[0];   // [32,4]
    const float* noise = (const float*)d_in[1];   // [32,64,20000]
    float* out = (float*)d_out;                   // [32,64,20000]
    (void)in_sizes; (void)n_in; (void)out_size;
    // 64-thread CTAs: 1024 blocks -> 6.92 CTAs/SM (1.2% imbalance vs 13.5%)
    oup_kernel<<<N_CHAIN / 2, 64>>>(theta, noise, out);
}